// round 4
// baseline (speedup 1.0000x reference)
#include <cuda_runtime.h>
#include <cuda_fp16.h>
#include <cstdint>

// ---------------- problem constants ----------------
#define NB   64
#define C    256
#define HH   28
#define WW   28
#define HW   784
#define MTOT (NB*HW)          // 50176

// ---------------- tiling ----------------
#define BM   128
#define BN   128
#define BK   64
#define NTILES (MTOT/BM)      // 392
#define NKCH 36               // 9 kk * 4 ci-chunks of 64
#define THREADS 128

#define STAGES 3
#define A_BYTES (BM*128)      // 16 KB (128 rows x 64 fp16)
#define B_BYTES (BN*128)      // 16 KB
#define STG (A_BYTES + B_BYTES)
#define SMEM_BYTES (STAGES*STG)   // 98304 -> 2 CTAs/SM

// ---------------- scratch ----------------
__device__ __half g_xh[(size_t)MTOT * C];    // x NHWC fp16
__device__ __half g_out1[(size_t)MTOT * C];  // conv1 out NHWC fp16
__device__ __half g_wp1[9 * C * C];          // sign(w1) [kk][co][ci]
__device__ __half g_wp2[9 * C * C];
__device__ float g_s1[C], g_bb1[C], g_s2[C], g_bb2[C];

// ---------------- ptx helpers ----------------
__device__ __forceinline__ uint32_t smem_u32(const void* p) {
    uint32_t a;
    asm("{ .reg .u64 t; cvta.to.shared.u64 t, %1; cvt.u32.u64 %0, t; }" : "=r"(a) : "l"(p));
    return a;
}
__device__ __forceinline__ void cp16(uint32_t dst, const void* src, bool pred) {
    int sz = pred ? 16 : 0;
    asm volatile("cp.async.cg.shared.global [%0], [%1], 16, %2;\n"
                 :: "r"(dst), "l"(src), "r"(sz));
}
__device__ __forceinline__ void cp_commit() { asm volatile("cp.async.commit_group;\n" ::); }
__device__ __forceinline__ void cp_wait1()  { asm volatile("cp.async.wait_group 1;\n" ::: "memory"); }

__device__ __forceinline__ void ldmx4(uint32_t* r, uint32_t addr) {
    asm volatile("ldmatrix.sync.aligned.m8n8.x4.shared.b16 {%0,%1,%2,%3}, [%4];"
        : "=r"(r[0]), "=r"(r[1]), "=r"(r[2]), "=r"(r[3]) : "r"(addr));
}
__device__ __forceinline__ void mma16816(float* c, const uint32_t* a, const uint32_t* b) {
    asm volatile("mma.sync.aligned.m16n8k16.row.col.f32.f16.f16.f32 "
        "{%0,%1,%2,%3}, {%4,%5,%6,%7}, {%8,%9}, {%0,%1,%2,%3};"
        : "+f"(c[0]), "+f"(c[1]), "+f"(c[2]), "+f"(c[3])
        : "r"(a[0]), "r"(a[1]), "r"(a[2]), "r"(a[3]), "r"(b[0]), "r"(b[1]));
}
#define SW(off) ((off) ^ (((off) >> 3) & 0x70))

// ---------------- prologue kernels ----------------
__global__ void bn_prep(const float* __restrict__ g1, const float* __restrict__ b1,
                        const float* __restrict__ m1, const float* __restrict__ v1,
                        const float* __restrict__ g2, const float* __restrict__ b2,
                        const float* __restrict__ m2, const float* __restrict__ v2) {
    int t = threadIdx.x;
    if (t < C) {
        float inv1 = g1[t] * rsqrtf(v1[t] + 1e-5f);
        g_s1[t]  = 0.02f * inv1;
        g_bb1[t] = b1[t] - m1[t] * inv1;
        float inv2 = g2[t] * rsqrtf(v2[t] + 1e-5f);
        g_s2[t]  = 0.02f * inv2;
        g_bb2[t] = b2[t] - m2[t] * inv2;
    }
}

// NCHW -> NHWC transpose, fp32 -> fp16
__global__ void xpose(const float* __restrict__ x) {
    __shared__ float t[32][33];
    int n = blockIdx.z, hwt = blockIdx.x, ct = blockIdx.y;
    int tx = threadIdx.x, ty = threadIdx.y;
    int hw = hwt * 32 + tx;
    #pragma unroll
    for (int i = 0; i < 4; i++) {
        int c = ct * 32 + ty + i * 8;
        t[ty + i * 8][tx] = (hw < HW) ? x[((size_t)n * C + c) * HW + hw] : 0.f;
    }
    __syncthreads();
    #pragma unroll
    for (int i = 0; i < 4; i++) {
        int hw2 = hwt * 32 + ty + i * 8;
        int c = ct * 32 + tx;
        if (hw2 < HW)
            g_xh[((size_t)n * HW + hw2) * C + c] = __float2half_rn(t[tx][ty + i * 8]);
    }
}

// sign(w) packed as [kk][co][ci] fp16; sign(0)=0 to match jnp.sign.
__global__ void packw(const float* __restrict__ w, int which) {
    int idx = blockIdx.x * 256 + threadIdx.x;   // < 9*256*256
    int kk  = idx >> 16;
    int rem = idx & 65535;
    int co  = rem >> 8;
    int ci  = rem & 255;
    float wv = w[(co * C + ci) * 9 + kk];
    float s = (wv > 0.f) ? 1.f : ((wv < 0.f) ? -1.f : 0.f);
    __half h = __float2half_rn(s);
    if (which == 0) g_wp1[idx] = h; else g_wp2[idx] = h;
}

// ---------------- main conv kernel (fp16 HMMA implicit GEMM) ----------------
// MODE 0: A=g_xh,  W=g_wp1, out = relu(bn1(conv))   -> g_out1 (NHWC fp16)
// MODE 1: A=g_out1,W=g_wp2, out = relu(bn2(conv)+x) -> d_out  (NCHW fp32)
template <int MODE>
__global__ void __launch_bounds__(THREADS, 2)
convk(const float* __restrict__ resid, float* __restrict__ out) {
    extern __shared__ char smem[];
    const uint32_t sb = smem_u32(smem);

    const __half* Ain = MODE ? g_out1 : g_xh;
    const __half* Wp  = MODE ? g_wp2  : g_wp1;
    const float*  sc  = MODE ? g_s2   : g_s1;
    const float*  bi  = MODE ? g_bb2  : g_bb1;

    const int tid  = threadIdx.x;
    const int wid  = tid >> 5, lane = tid & 31;
    const int bn   = blockIdx.x;    // 0..1
    const int bm   = blockIdx.y;    // 0..391

    // --- loader geometry: thread t loads A row t and B row t (128B each) ---
    const int m  = bm * BM + tid;
    const int n  = m / HW;
    const int hw = m - n * HW;
    const int h  = hw / WW;
    const int w  = hw - h * WW;
    const __half* arow = Ain + (size_t)m * C;
    const __half* brow = Wp + (size_t)(bn * BN + tid) * C;

    auto loadStage = [&](int kc) {
        const int s  = kc % STAGES;
        const int kk = kc >> 2, ck = kc & 3;
        const int dh = kk / 3 - 1;
        const int dw = kk - (kk / 3) * 3 - 1;
        const uint32_t aB = sb + s * STG;
        const uint32_t bB = aB + A_BYTES;

        const bool valid = ((unsigned)(h + dh) < HH) && ((unsigned)(w + dw) < WW);
        const __half* asrc = valid ? (arow + (dh * WW + dw) * C + ck * 64) : (const __half*)Wp;
        const uint32_t ra = (uint32_t)tid * 128;
        #pragma unroll
        for (int i = 0; i < 8; i++) {
            uint32_t off = ra + i * 16;
            cp16(aB + SW(off), asrc + i * 8, valid);
        }
        const __half* bs = brow + (size_t)kk * (C * C) + ck * 64;
        #pragma unroll
        for (int i = 0; i < 8; i++) {
            uint32_t off = ra + i * 16;
            cp16(bB + SW(off), bs + i * 8, true);
        }
        cp_commit();
    };

    // --- compute geometry: 4 warps in 2x2, each 64x64 ---
    const int wm = wid & 1;           // m 64-half
    const int wn = wid >> 1;          // n 64-half
    const int lq = lane >> 3;         // quad
    const int l7 = lane & 7;
    const int aro = (lq & 1) * 8 + l7;     // A ldmatrix row offset
    const int aqh = lq >> 1;               // A k-16B-half select
    const int bro = (lq >> 1) * 8 + l7;    // B ldmatrix row offset
    const int bqh = lq & 1;                // B k-16B-half select

    float acc[4][8][4];
    #pragma unroll
    for (int i = 0; i < 4; i++)
        #pragma unroll
        for (int j = 0; j < 8; j++)
            #pragma unroll
            for (int k = 0; k < 4; k++) acc[i][j][k] = 0.f;

    loadStage(0);
    loadStage(1);

    for (int kc = 0; kc < NKCH; kc++) {
        cp_wait1();                 // stage kc resident (always 2 groups ahead)
        __syncthreads();            // everyone done reading stage (kc-1) & sees stage kc
        if (kc + 2 < NKCH) loadStage(kc + 2); else cp_commit();

        const int s = kc % STAGES;
        const uint32_t aB = sb + s * STG + (uint32_t)(wm * 64) * 128;
        const uint32_t bB = sb + s * STG + A_BYTES + (uint32_t)(wn * 64) * 128;

        #pragma unroll
        for (int ks = 0; ks < 4; ks++) {
            uint32_t af[4][4];
            #pragma unroll
            for (int mt = 0; mt < 4; mt++) {
                int row = mt * 16 + aro;
                uint32_t cx = (uint32_t)(((ks * 2 + aqh) ^ (row & 7)) * 16);
                ldmx4(af[mt], aB + (uint32_t)row * 128 + cx);
            }
            uint32_t bf[4][4];
            #pragma unroll
            for (int nt2 = 0; nt2 < 4; nt2++) {
                int row = nt2 * 16 + bro;
                uint32_t cx = (uint32_t)(((ks * 2 + bqh) ^ (row & 7)) * 16);
                ldmx4(bf[nt2], bB + (uint32_t)row * 128 + cx);
            }
            #pragma unroll
            for (int mt = 0; mt < 4; mt++)
                #pragma unroll
                for (int nt = 0; nt < 8; nt++)
                    mma16816(acc[mt][nt], af[mt], &bf[nt >> 1][(nt & 1) * 2]);
        }
    }

    // ---------------- epilogue ----------------
    const int lr = lane >> 2;        // 0..7 (row in 8x8 tile)
    const int lc = (lane & 3) * 2;   // col pair

    if (MODE == 0) {
        const int mbase  = bm * BM + wm * 64;
        const int cobase = bn * BN + wn * 64;
        #pragma unroll
        for (int nt = 0; nt < 8; nt++) {
            const int co = cobase + nt * 8 + lc;
            const float s0 = sc[co],   s1 = sc[co + 1];
            const float c0 = bi[co],   c1 = bi[co + 1];
            #pragma unroll
            for (int mt = 0; mt < 4; mt++) {
                const int m0 = mbase + mt * 16 + lr;
                float v0 = fmaxf(acc[mt][nt][0] * s0 + c0, 0.f);
                float v1 = fmaxf(acc[mt][nt][1] * s1 + c1, 0.f);
                float v2 = fmaxf(acc[mt][nt][2] * s0 + c0, 0.f);
                float v3 = fmaxf(acc[mt][nt][3] * s1 + c1, 0.f);
                *(__half2*)&g_out1[(size_t)m0 * C + co]       = __floats2half2_rn(v0, v1);
                *(__half2*)&g_out1[(size_t)(m0 + 8) * C + co] = __floats2half2_rn(v2, v3);
            }
        }
    } else {
        // transpose through smem -> coalesced NCHW float4 stores with residual
        __syncthreads();             // mainloop fully done before smem reuse
        float* st = (float*)smem;    // [co 128][m 128] stride 132 floats (67.6 KB)
        #pragma unroll
        for (int nt = 0; nt < 8; nt++) {
            const int col = wn * 64 + nt * 8 + lc;
            const int gco = bn * BN + col;
            const float s0 = sc[gco],   s1 = sc[gco + 1];
            const float c0 = bi[gco],   c1 = bi[gco + 1];
            #pragma unroll
            for (int mt = 0; mt < 4; mt++) {
                const int ml = wm * 64 + mt * 16 + lr;
                st[col * 132 + ml]           = acc[mt][nt][0] * s0 + c0;
                st[(col + 1) * 132 + ml]     = acc[mt][nt][1] * s1 + c1;
                st[col * 132 + ml + 8]       = acc[mt][nt][2] * s0 + c0;
                st[(col + 1) * 132 + ml + 8] = acc[mt][nt][3] * s1 + c1;
            }
        }
        __syncthreads();
        #pragma unroll
        for (int p = 0; p < 8; p++) {
            const int col = p * 16 + (tid >> 3);
            const int gco = bn * BN + col;
            #pragma unroll
            for (int j = 0; j < 4; j++) {
                const int ml = ((tid & 7) + j * 8) * 4;
                const int mg = bm * BM + ml;
                const int n2 = mg / HW;
                const int hw2 = mg - n2 * HW;
                const size_t gi = (size_t)n2 * (C * HW) + (size_t)gco * HW + hw2;
                float4 r = *(const float4*)&resid[gi];
                float4 v = *(const float4*)&st[col * 132 + ml];
                float4 o;
                o.x = fmaxf(v.x + r.x, 0.f);
                o.y = fmaxf(v.y + r.y, 0.f);
                o.z = fmaxf(v.z + r.z, 0.f);
                o.w = fmaxf(v.w + r.w, 0.f);
                *(float4*)&out[gi] = o;
            }
        }
    }
}

// ---------------- launch ----------------
extern "C" void kernel_launch(void* const* d_in, const int* in_sizes, int n_in,
                              void* d_out, int out_size) {
    (void)in_sizes; (void)n_in; (void)out_size;
    const float* x  = (const float*)d_in[0];
    const float* w1 = (const float*)d_in[1];
    const float* g1 = (const float*)d_in[2];
    const float* b1 = (const float*)d_in[3];
    const float* m1 = (const float*)d_in[4];
    const float* v1 = (const float*)d_in[5];
    const float* w2 = (const float*)d_in[6];
    const float* g2 = (const float*)d_in[7];
    const float* b2 = (const float*)d_in[8];
    const float* m2 = (const float*)d_in[9];
    const float* v2 = (const float*)d_in[10];
    float* out = (float*)d_out;

    cudaFuncSetAttribute(convk<0>, cudaFuncAttributeMaxDynamicSharedMemorySize, SMEM_BYTES);
    cudaFuncSetAttribute(convk<1>, cudaFuncAttributeMaxDynamicSharedMemorySize, SMEM_BYTES);

    bn_prep<<<1, 256>>>(g1, b1, m1, v1, g2, b2, m2, v2);
    xpose<<<dim3(25, 8, 64), dim3(32, 8)>>>(x);
    packw<<<2304, 256>>>(w1, 0);
    packw<<<2304, 256>>>(w2, 1);

    dim3 grid(2, NTILES);   // (bn, bm)
    convk<0><<<grid, THREADS, SMEM_BYTES>>>(nullptr, nullptr);
    convk<1><<<grid, THREADS, SMEM_BYTES>>>(x, out);
}

// round 5
// speedup vs baseline: 1.0498x; 1.0498x over previous
#include <cuda_runtime.h>
#include <cuda_fp16.h>
#include <cstdint>

// ---------------- problem constants ----------------
#define NB   64
#define C    256
#define HH   28
#define WW   28
#define HW   784
#define MTOT (NB*HW)          // 50176

// ---------------- tiling ----------------
#define BM   128
#define BN   128
#define NTILES (MTOT/BM)      // 392
#define NKCH 36               // 9 kk * 4 ci-chunks of 64
#define THREADS 256

#define STAGES 3
#define A_BYTES (BM*128)      // 16 KB
#define B_BYTES (BN*128)      // 16 KB
#define STG (A_BYTES + B_BYTES)
#define SMEM_BYTES (STAGES*STG)   // 98304

// ---------------- scratch ----------------
__device__ __half g_xh[(size_t)MTOT * C];    // x NHWC fp16
__device__ __half g_out1[(size_t)MTOT * C];  // conv1 out NHWC fp16
__device__ __half g_wp1[9 * C * C];          // sign(w1) [kk][co][ci]
__device__ __half g_wp2[9 * C * C];
__device__ float g_s1[C], g_bb1[C], g_s2[C], g_bb2[C];

// ---------------- ptx helpers ----------------
__device__ __forceinline__ uint32_t smem_u32(const void* p) {
    uint32_t a;
    asm("{ .reg .u64 t; cvta.to.shared.u64 t, %1; cvt.u32.u64 %0, t; }" : "=r"(a) : "l"(p));
    return a;
}
__device__ __forceinline__ void cp16(uint32_t dst, const void* src, bool pred) {
    int sz = pred ? 16 : 0;
    asm volatile("cp.async.cg.shared.global [%0], [%1], 16, %2;\n"
                 :: "r"(dst), "l"(src), "r"(sz));
}
__device__ __forceinline__ void cp_commit() { asm volatile("cp.async.commit_group;\n" ::); }
__device__ __forceinline__ void cp_wait1()  { asm volatile("cp.async.wait_group 1;\n" ::: "memory"); }

__device__ __forceinline__ void ldmx4(uint32_t* r, uint32_t addr) {
    asm volatile("ldmatrix.sync.aligned.m8n8.x4.shared.b16 {%0,%1,%2,%3}, [%4];"
        : "=r"(r[0]), "=r"(r[1]), "=r"(r[2]), "=r"(r[3]) : "r"(addr));
}
// fp16 accumulator mma: D,C are 2 regs of f16x2
__device__ __forceinline__ void mma16816_h(uint32_t* c, const uint32_t* a, const uint32_t* b) {
    asm volatile("mma.sync.aligned.m16n8k16.row.col.f16.f16.f16.f16 "
        "{%0,%1}, {%2,%3,%4,%5}, {%6,%7}, {%0,%1};"
        : "+r"(c[0]), "+r"(c[1])
        : "r"(a[0]), "r"(a[1]), "r"(a[2]), "r"(a[3]), "r"(b[0]), "r"(b[1]));
}
#define SW(off) ((off) ^ (((off) >> 3) & 0x70))

// ---------------- prologue kernels ----------------
__global__ void bn_prep(const float* __restrict__ g1, const float* __restrict__ b1,
                        const float* __restrict__ m1, const float* __restrict__ v1,
                        const float* __restrict__ g2, const float* __restrict__ b2,
                        const float* __restrict__ m2, const float* __restrict__ v2) {
    int t = threadIdx.x;
    if (t < C) {
        float inv1 = g1[t] * rsqrtf(v1[t] + 1e-5f);
        g_s1[t]  = 0.02f * inv1;
        g_bb1[t] = b1[t] - m1[t] * inv1;
        float inv2 = g2[t] * rsqrtf(v2[t] + 1e-5f);
        g_s2[t]  = 0.02f * inv2;
        g_bb2[t] = b2[t] - m2[t] * inv2;
    }
}

__global__ void xpose(const float* __restrict__ x) {
    __shared__ float t[32][33];
    int n = blockIdx.z, hwt = blockIdx.x, ct = blockIdx.y;
    int tx = threadIdx.x, ty = threadIdx.y;
    int hw = hwt * 32 + tx;
    #pragma unroll
    for (int i = 0; i < 4; i++) {
        int c = ct * 32 + ty + i * 8;
        t[ty + i * 8][tx] = (hw < HW) ? x[((size_t)n * C + c) * HW + hw] : 0.f;
    }
    __syncthreads();
    #pragma unroll
    for (int i = 0; i < 4; i++) {
        int hw2 = hwt * 32 + ty + i * 8;
        int c = ct * 32 + tx;
        if (hw2 < HW)
            g_xh[((size_t)n * HW + hw2) * C + c] = __float2half_rn(t[tx][ty + i * 8]);
    }
}

__global__ void packw(const float* __restrict__ w, int which) {
    int idx = blockIdx.x * 256 + threadIdx.x;
    int kk  = idx >> 16;
    int rem = idx & 65535;
    int co  = rem >> 8;
    int ci  = rem & 255;
    float wv = w[(co * C + ci) * 9 + kk];
    float s = (wv > 0.f) ? 1.f : ((wv < 0.f) ? -1.f : 0.f);
    __half h = __float2half_rn(s);
    if (which == 0) g_wp1[idx] = h; else g_wp2[idx] = h;
}

// ---------------- main conv kernel ----------------
// 8 warps (2m x 4n), warp tile 64x32. f16 accumulate per K=64 chunk, f32 promote.
template <int MODE>
__global__ void __launch_bounds__(THREADS, 1)
convk(const float* __restrict__ resid, float* __restrict__ out) {
    extern __shared__ char smem[];
    const uint32_t sb = smem_u32(smem);

    const __half* Ain = MODE ? g_out1 : g_xh;
    const __half* Wp  = MODE ? g_wp2  : g_wp1;
    const float*  sc  = MODE ? g_s2   : g_s1;
    const float*  bi  = MODE ? g_bb2  : g_bb1;

    const int tid  = threadIdx.x;
    const int wid  = tid >> 5, lane = tid & 31;
    const int bn   = blockIdx.x;    // 0..1
    const int bm   = blockIdx.y;    // 0..391

    // --- loader geometry: thread t loads 64B of A row (t>>1) and B row (t>>1) ---
    const int lrow = tid >> 1;
    const int lhalf = tid & 1;
    const int m  = bm * BM + lrow;
    const int n  = m / HW;
    const int hw = m - n * HW;
    const int h  = hw / WW;
    const int w  = hw - h * WW;
    const __half* arow = Ain + (size_t)m * C + lhalf * 32;
    const __half* brow = Wp + (size_t)(bn * BN + lrow) * C + lhalf * 32;

    auto loadStage = [&](int kc) {
        const int s  = kc % STAGES;
        const int kk = kc >> 2, ck = kc & 3;
        const int dh = kk / 3 - 1;
        const int dw = kk - (kk / 3) * 3 - 1;
        const uint32_t aB = sb + s * STG;
        const uint32_t bB = aB + A_BYTES;

        const bool valid = ((unsigned)(h + dh) < HH) && ((unsigned)(w + dw) < WW);
        const __half* asrc = valid ? (arow + (dh * WW + dw) * C + ck * 64) : (const __half*)Wp;
        const uint32_t ra = (uint32_t)lrow * 128 + lhalf * 64;
        #pragma unroll
        for (int i = 0; i < 4; i++) {
            uint32_t off = ra + i * 16;
            cp16(aB + SW(off), asrc + i * 8, valid);
        }
        const __half* bs = brow + (size_t)kk * (C * C) + ck * 64;
        #pragma unroll
        for (int i = 0; i < 4; i++) {
            uint32_t off = ra + i * 16;
            cp16(bB + SW(off), bs + i * 8, true);
        }
        cp_commit();
    };

    // --- compute geometry: warp (wm, wn), tile 64(m) x 32(n) ---
    const int wm = wid & 1;           // 0..1
    const int wn = wid >> 1;          // 0..3
    const int lq = lane >> 3;
    const int l7 = lane & 7;
    const int aro = (lq & 1) * 8 + l7;
    const int aqh = lq >> 1;
    const int bro = (lq >> 1) * 8 + l7;
    const int bqh = lq & 1;

    float acc[4][4][4];
    #pragma unroll
    for (int i = 0; i < 4; i++)
        #pragma unroll
        for (int j = 0; j < 4; j++)
            #pragma unroll
            for (int k = 0; k < 4; k++) acc[i][j][k] = 0.f;

    loadStage(0);
    loadStage(1);

    for (int kc = 0; kc < NKCH; kc++) {
        cp_wait1();
        __syncthreads();
        if (kc + 2 < NKCH) loadStage(kc + 2); else cp_commit();

        const int s = kc % STAGES;
        const uint32_t aB = sb + s * STG + (uint32_t)(wm * 64) * 128;
        const uint32_t bB = sb + s * STG + A_BYTES + (uint32_t)(wn * 32) * 128;

        // f16 accumulators for this chunk (K=64)
        uint32_t hacc[4][4][2];
        #pragma unroll
        for (int mt = 0; mt < 4; mt++)
            #pragma unroll
            for (int nt = 0; nt < 4; nt++) { hacc[mt][nt][0] = 0u; hacc[mt][nt][1] = 0u; }

        #pragma unroll
        for (int ks = 0; ks < 4; ks++) {
            uint32_t af[4][4];
            #pragma unroll
            for (int mt = 0; mt < 4; mt++) {
                int row = mt * 16 + aro;
                uint32_t cx = (uint32_t)(((ks * 2 + aqh) ^ (row & 7)) * 16);
                ldmx4(af[mt], aB + (uint32_t)row * 128 + cx);
            }
            uint32_t bf[2][4];
            #pragma unroll
            for (int nt2 = 0; nt2 < 2; nt2++) {
                int row = nt2 * 16 + bro;
                uint32_t cx = (uint32_t)(((ks * 2 + bqh) ^ (row & 7)) * 16);
                ldmx4(bf[nt2], bB + (uint32_t)row * 128 + cx);
            }
            #pragma unroll
            for (int mt = 0; mt < 4; mt++)
                #pragma unroll
                for (int nt = 0; nt < 4; nt++)
                    mma16816_h(hacc[mt][nt], af[mt], &bf[nt >> 1][(nt & 1) * 2]);
        }

        // promote chunk f16 partials into f32 accumulators
        #pragma unroll
        for (int mt = 0; mt < 4; mt++)
            #pragma unroll
            for (int nt = 0; nt < 4; nt++) {
                float2 f0 = __half22float2(*(__half2*)&hacc[mt][nt][0]);
                float2 f1 = __half22float2(*(__half2*)&hacc[mt][nt][1]);
                acc[mt][nt][0] += f0.x;
                acc[mt][nt][1] += f0.y;
                acc[mt][nt][2] += f1.x;
                acc[mt][nt][3] += f1.y;
            }
    }

    // ---------------- epilogue ----------------
    const int lr = lane >> 2;        // 0..7
    const int lc = (lane & 3) * 2;   // col pair

    if (MODE == 0) {
        const int mbase  = bm * BM + wm * 64;
        const int cobase = bn * BN + wn * 32;
        #pragma unroll
        for (int nt = 0; nt < 4; nt++) {
            const int co = cobase + nt * 8 + lc;
            const float s0 = sc[co],   s1 = sc[co + 1];
            const float c0 = bi[co],   c1 = bi[co + 1];
            #pragma unroll
            for (int mt = 0; mt < 4; mt++) {
                const int m0 = mbase + mt * 16 + lr;
                float v0 = fmaxf(acc[mt][nt][0] * s0 + c0, 0.f);
                float v1 = fmaxf(acc[mt][nt][1] * s1 + c1, 0.f);
                float v2 = fmaxf(acc[mt][nt][2] * s0 + c0, 0.f);
                float v3 = fmaxf(acc[mt][nt][3] * s1 + c1, 0.f);
                *(__half2*)&g_out1[(size_t)m0 * C + co]       = __floats2half2_rn(v0, v1);
                *(__half2*)&g_out1[(size_t)(m0 + 8) * C + co] = __floats2half2_rn(v2, v3);
            }
        }
    } else {
        __syncthreads();
        float* st = (float*)smem;    // [co 128][m 128] stride 132 (67.6 KB)
        #pragma unroll
        for (int nt = 0; nt < 4; nt++) {
            const int col = wn * 32 + nt * 8 + lc;
            const int gco = bn * BN + col;
            const float s0 = sc[gco],   s1 = sc[gco + 1];
            const float c0 = bi[gco],   c1 = bi[gco + 1];
            #pragma unroll
            for (int mt = 0; mt < 4; mt++) {
                const int ml = wm * 64 + mt * 16 + lr;
                st[col * 132 + ml]           = acc[mt][nt][0] * s0 + c0;
                st[(col + 1) * 132 + ml]     = acc[mt][nt][1] * s1 + c1;
                st[col * 132 + ml + 8]       = acc[mt][nt][2] * s0 + c0;
                st[(col + 1) * 132 + ml + 8] = acc[mt][nt][3] * s1 + c1;
            }
        }
        __syncthreads();
        #pragma unroll
        for (int p = 0; p < 4; p++) {
            const int col = p * 32 + (tid >> 3);
            const int gco = bn * BN + col;
            #pragma unroll
            for (int j = 0; j < 4; j++) {
                const int ml = ((tid & 7) + j * 8) * 4;
                const int mg = bm * BM + ml;
                const int n2 = mg / HW;
                const int hw2 = mg - n2 * HW;
                const size_t gi = (size_t)n2 * (C * HW) + (size_t)gco * HW + hw2;
                float4 r = *(const float4*)&resid[gi];
                float4 v = *(const float4*)&st[col * 132 + ml];
                float4 o;
                o.x = fmaxf(v.x + r.x, 0.f);
                o.y = fmaxf(v.y + r.y, 0.f);
                o.z = fmaxf(v.z + r.z, 0.f);
                o.w = fmaxf(v.w + r.w, 0.f);
                *(float4*)&out[gi] = o;
            }
        }
    }
}

// ---------------- launch ----------------
extern "C" void kernel_launch(void* const* d_in, const int* in_sizes, int n_in,
                              void* d_out, int out_size) {
    (void)in_sizes; (void)n_in; (void)out_size;
    const float* x  = (const float*)d_in[0];
    const float* w1 = (const float*)d_in[1];
    const float* g1 = (const float*)d_in[2];
    const float* b1 = (const float*)d_in[3];
    const float* m1 = (const float*)d_in[4];
    const float* v1 = (const float*)d_in[5];
    const float* w2 = (const float*)d_in[6];
    const float* g2 = (const float*)d_in[7];
    const float* b2 = (const float*)d_in[8];
    const float* m2 = (const float*)d_in[9];
    const float* v2 = (const float*)d_in[10];
    float* out = (float*)d_out;

    cudaFuncSetAttribute(convk<0>, cudaFuncAttributeMaxDynamicSharedMemorySize, SMEM_BYTES);
    cudaFuncSetAttribute(convk<1>, cudaFuncAttributeMaxDynamicSharedMemorySize, SMEM_BYTES);

    bn_prep<<<1, 256>>>(g1, b1, m1, v1, g2, b2, m2, v2);
    xpose<<<dim3(25, 8, 64), dim3(32, 8)>>>(x);
    packw<<<2304, 256>>>(w1, 0);
    packw<<<2304, 256>>>(w2, 1);

    dim3 grid(2, NTILES);   // (bn, bm)
    convk<0><<<grid, THREADS, SMEM_BYTES>>>(nullptr, nullptr);
    convk<1><<<grid, THREADS, SMEM_BYTES>>>(x, out);
}

// round 7
// speedup vs baseline: 1.5070x; 1.4355x over previous
#include <cuda_runtime.h>
#include <cuda_fp16.h>
#include <cstdint>

// ---------------- constants ----------------
#define C     256
#define NB    64
#define HW    784
#define NPAD  900                 // 30*30 padded image
#define PADROWS (NB*NPAD)         // 57600
#define NTT   12544               // total 2x2 tiles = 64*14*14
#define VSTRIDE ((size_t)NTT*C)   // 3211264

// ---------------- device scratch (only touched from device code!) ----------------
__device__ __half g_xh[PADROWS*C];   // padded NHWC input fp16 (halo stays 0)
__device__ __half g_o1[PADROWS*C];   // padded conv1 output fp16 (halo stays 0)
__device__ __half g_U1[16*C*C];      // transformed weights GgG^T
__device__ __half g_U2[16*C*C];
__device__ __half g_V[16*NTT*C];     // input transform (fp16)
__device__ float  g_Mf[16*NTT*C];    // gemm output (fp32 for numerics)
__device__ float g_s1[C], g_b1[C], g_s2[C], g_b2[C];

// ---------------- ptx helpers ----------------
__device__ __forceinline__ uint32_t smem_u32(const void* p) {
    uint32_t a;
    asm("{ .reg .u64 t; cvta.to.shared.u64 t, %1; cvt.u32.u64 %0, t; }" : "=r"(a) : "l"(p));
    return a;
}
__device__ __forceinline__ void cp16(uint32_t dst, const void* src) {
    asm volatile("cp.async.cg.shared.global [%0], [%1], 16;\n" :: "r"(dst), "l"(src));
}
__device__ __forceinline__ void cp_commit() { asm volatile("cp.async.commit_group;\n" ::); }
template<int N> __device__ __forceinline__ void cp_waitg() {
    asm volatile("cp.async.wait_group %0;\n" :: "n"(N) : "memory");
}
__device__ __forceinline__ void ldmx4(uint32_t* r, uint32_t addr) {
    asm volatile("ldmatrix.sync.aligned.m8n8.x4.shared.b16 {%0,%1,%2,%3}, [%4];"
        : "=r"(r[0]), "=r"(r[1]), "=r"(r[2]), "=r"(r[3]) : "r"(addr));
}
__device__ __forceinline__ void mma16816_h(uint32_t* c, const uint32_t* a, const uint32_t* b) {
    asm volatile("mma.sync.aligned.m16n8k16.row.col.f16.f16.f16.f16 "
        "{%0,%1}, {%2,%3,%4,%5}, {%6,%7}, {%0,%1};"
        : "+r"(c[0]), "+r"(c[1])
        : "r"(a[0]), "r"(a[1]), "r"(a[2]), "r"(a[3]), "r"(b[0]), "r"(b[1]));
}
#define SW(off) ((off) ^ (((off) >> 3) & 0x70))

// ---------------- prep: BN consts + weight transform U = G g G^T ----------------
__global__ void prep(const float* __restrict__ w1, const float* __restrict__ w2,
                     const float* __restrict__ g1, const float* __restrict__ b1,
                     const float* __restrict__ m1, const float* __restrict__ v1,
                     const float* __restrict__ g2, const float* __restrict__ b2,
                     const float* __restrict__ m2, const float* __restrict__ v2) {
    int co = blockIdx.x, which = blockIdx.y, ci = threadIdx.x;
    if (co == 256) {
        if (which == 0) {
            float inv = g1[ci] * rsqrtf(v1[ci] + 1e-5f);
            g_s1[ci] = 0.02f * inv; g_b1[ci] = b1[ci] - m1[ci] * inv;
        } else {
            float inv = g2[ci] * rsqrtf(v2[ci] + 1e-5f);
            g_s2[ci] = 0.02f * inv; g_b2[ci] = b2[ci] - m2[ci] * inv;
        }
        return;
    }
    const float* w = which ? w2 : w1;
    __half* U = which ? g_U2 : g_U1;
    float g[3][3];
    #pragma unroll
    for (int r = 0; r < 3; r++)
        #pragma unroll
        for (int c = 0; c < 3; c++) {
            float v = w[((co * C + ci) * 3 + r) * 3 + c];
            g[r][c] = (v > 0.f) ? 1.f : ((v < 0.f) ? -1.f : 0.f);
        }
    float T[4][3];
    #pragma unroll
    for (int c = 0; c < 3; c++) {
        T[0][c] = g[0][c];
        T[1][c] = 0.5f * (g[0][c] + g[1][c] + g[2][c]);
        T[2][c] = 0.5f * (g[0][c] - g[1][c] + g[2][c]);
        T[3][c] = g[2][c];
    }
    #pragma unroll
    for (int i = 0; i < 4; i++) {
        float u0 = T[i][0];
        float u1 = 0.5f * (T[i][0] + T[i][1] + T[i][2]);
        float u2 = 0.5f * (T[i][0] - T[i][1] + T[i][2]);
        float u3 = T[i][2];
        int base = co * C + ci;
        U[(i * 4 + 0) * (C * C) + base] = __float2half_rn(u0);
        U[(i * 4 + 1) * (C * C) + base] = __float2half_rn(u1);
        U[(i * 4 + 2) * (C * C) + base] = __float2half_rn(u2);
        U[(i * 4 + 3) * (C * C) + base] = __float2half_rn(u3);
    }
}

// ---------------- NCHW -> padded NHWC fp16 ----------------
__global__ void xpose(const float* __restrict__ x) {
    __shared__ float t[32][33];
    int n = blockIdx.z, hwt = blockIdx.x, ct = blockIdx.y;
    int tx = threadIdx.x, ty = threadIdx.y;
    int hw = hwt * 32 + tx;
    #pragma unroll
    for (int i = 0; i < 4; i++) {
        int c = ct * 32 + ty + i * 8;
        t[ty + i * 8][tx] = (hw < HW) ? x[((size_t)n * C + c) * HW + hw] : 0.f;
    }
    __syncthreads();
    #pragma unroll
    for (int i = 0; i < 4; i++) {
        int hw2 = hwt * 32 + ty + i * 8;
        int c = ct * 32 + tx;
        if (hw2 < HW) {
            int h = hw2 / 28, w = hw2 - h * 28;
            g_xh[((size_t)(n * NPAD + (h + 1) * 30 + w + 1)) * C + c] =
                __float2half_rn(t[tx][ty + i * 8]);
        }
    }
}

// ---------------- input transform: V = B^T d B ----------------
// block 256 = 8 tile-slots x 32 ci-octets; grid 1568
template <int WHICH>
__global__ __launch_bounds__(256) void wino_in() {
    const __half* src = WHICH ? g_o1 : g_xh;
    int t = threadIdx.x;
    int cig = t & 31, slot = t >> 5;
    int mp = blockIdx.x * 8 + slot;
    int n = mp / 196; int r0 = mp - n * 196;
    int ti = r0 / 14, tj = r0 - ti * 14;
    const __half* base = src + ((size_t)(n * NPAD + 2 * ti * 30 + 2 * tj)) * C + cig * 8;

    uint4 d16[16];
    #pragma unroll
    for (int i = 0; i < 4; i++)
        #pragma unroll
        for (int j = 0; j < 4; j++)
            d16[i * 4 + j] = *(const uint4*)(base + (size_t)(i * 30 + j) * C);

    __half2 vout[16][4];
    #pragma unroll
    for (int k = 0; k < 8; k++) {
        float d[4][4];
        #pragma unroll
        for (int p = 0; p < 16; p++) {
            uint32_t wd = ((const uint32_t*)&d16[p])[k >> 1];
            float2 f = __half22float2(*(__half2*)&wd);
            d[p >> 2][p & 3] = (k & 1) ? f.y : f.x;
        }
        float tt[4][4];
        #pragma unroll
        for (int c = 0; c < 4; c++) {
            tt[0][c] = d[0][c] - d[2][c];
            tt[1][c] = d[1][c] + d[2][c];
            tt[2][c] = d[2][c] - d[1][c];
            tt[3][c] = d[1][c] - d[3][c];
        }
        #pragma unroll
        for (int i = 0; i < 4; i++) {
            float v[4];
            v[0] = tt[i][0] - tt[i][2];
            v[1] = tt[i][1] + tt[i][2];
            v[2] = tt[i][2] - tt[i][1];
            v[3] = tt[i][1] - tt[i][3];
            #pragma unroll
            for (int j = 0; j < 4; j++) {
                __half hv = __float2half_rn(v[j]);
                int nu = i * 4 + j, wdi = k >> 1;
                if ((k & 1) == 0) vout[nu][wdi] = __halves2half2(hv, hv);
                else vout[nu][wdi] = __halves2half2(__low2half(vout[nu][wdi]), hv);
            }
        }
    }
    size_t mo = (size_t)mp * C + cig * 8;
    #pragma unroll
    for (int nu = 0; nu < 16; nu++)
        *(uint4*)(g_V + nu * VSTRIDE + mo) = *(uint4*)vout[nu];
}

// ---------------- batched GEMM: M[nu] = V[nu] * U[nu]^T ----------------
// grid (2, 98, 16), block 256 (8 warps 2x4, warp tile 64x32), smem 128KB
template <int WHICH>
__global__ __launch_bounds__(256, 1) void gemm_wino() {
    extern __shared__ char smem[];
    const uint32_t sb = smem_u32(smem);
    const int bn_ = blockIdx.x, bm = blockIdx.y, nu = blockIdx.z;
    const __half* Vb = g_V + (size_t)nu * VSTRIDE;
    const __half* Ub = (WHICH ? g_U2 : g_U1) + (size_t)nu * (C * C);

    const int tid = threadIdx.x;
    const int wid = tid >> 5, lane = tid & 31;
    const int row = tid >> 1, hf = tid & 1;
    const __half* Arow = Vb + (size_t)(bm * 128 + row) * C + hf * 32;
    const __half* Brow = Ub + (size_t)(bn_ * 128 + row) * C + hf * 32;

    // stage all 4 K-chunks (A: 0..64KB, B: 64..128KB)
    #pragma unroll
    for (int k = 0; k < 4; k++) {
        const uint32_t ro = (uint32_t)row * 128 + hf * 64;
        #pragma unroll
        for (int i = 0; i < 4; i++) {
            uint32_t o = ro + i * 16;
            cp16(sb + k * 16384 + SW(o), Arow + k * 64 + i * 8);
            cp16(sb + 65536 + k * 16384 + SW(o), Brow + k * 64 + i * 8);
        }
        cp_commit();
    }

    const int wm = wid & 1, wn = wid >> 1;
    const int lq = lane >> 3, l7 = lane & 7;
    const int aro = (lq & 1) * 8 + l7, aqh = lq >> 1;
    const int bro = (lq >> 1) * 8 + l7, bqh = lq & 1;

    float acc[4][4][4];
    #pragma unroll
    for (int i = 0; i < 4; i++)
        #pragma unroll
        for (int j = 0; j < 4; j++)
            #pragma unroll
            for (int k = 0; k < 4; k++) acc[i][j][k] = 0.f;

    #pragma unroll
    for (int k = 0; k < 4; k++) {
        if (k == 0) cp_waitg<3>();
        else if (k == 1) cp_waitg<2>();
        else if (k == 2) cp_waitg<1>();
        else cp_waitg<0>();
        __syncthreads();

        const uint32_t aB = sb + k * 16384 + (uint32_t)(wm * 64) * 128;
        const uint32_t bB = sb + 65536 + k * 16384 + (uint32_t)(wn * 32) * 128;

        uint32_t hacc[4][4][2];
        #pragma unroll
        for (int mt = 0; mt < 4; mt++)
            #pragma unroll
            for (int nt = 0; nt < 4; nt++) { hacc[mt][nt][0] = 0u; hacc[mt][nt][1] = 0u; }

        #pragma unroll
        for (int ks = 0; ks < 4; ks++) {
            uint32_t af[4][4];
            #pragma unroll
            for (int mt = 0; mt < 4; mt++) {
                int rw = mt * 16 + aro;
                uint32_t cx = (uint32_t)(((ks * 2 + aqh) ^ (rw & 7)) * 16);
                ldmx4(af[mt], aB + (uint32_t)rw * 128 + cx);
            }
            uint32_t bf[2][4];
            #pragma unroll
            for (int nt2 = 0; nt2 < 2; nt2++) {
                int rw = nt2 * 16 + bro;
                uint32_t cx = (uint32_t)(((ks * 2 + bqh) ^ (rw & 7)) * 16);
                ldmx4(bf[nt2], bB + (uint32_t)rw * 128 + cx);
            }
            #pragma unroll
            for (int mt = 0; mt < 4; mt++)
                #pragma unroll
                for (int nt = 0; nt < 4; nt++)
                    mma16816_h(hacc[mt][nt], af[mt], &bf[nt >> 1][(nt & 1) * 2]);
        }
        #pragma unroll
        for (int mt = 0; mt < 4; mt++)
            #pragma unroll
            for (int nt = 0; nt < 4; nt++) {
                float2 f0 = __half22float2(*(__half2*)&hacc[mt][nt][0]);
                float2 f1 = __half22float2(*(__half2*)&hacc[mt][nt][1]);
                acc[mt][nt][0] += f0.x; acc[mt][nt][1] += f0.y;
                acc[mt][nt][2] += f1.x; acc[mt][nt][3] += f1.y;
            }
    }

    // epilogue: fp32 M
    const int lr = lane >> 2, lc = (lane & 3) * 2;
    float* Mb = g_Mf + (size_t)nu * VSTRIDE;
    #pragma unroll
    for (int nt = 0; nt < 4; nt++) {
        const int co = bn_ * 128 + wn * 32 + nt * 8 + lc;
        #pragma unroll
        for (int mt = 0; mt < 4; mt++) {
            const int m0 = bm * 128 + wm * 64 + mt * 16 + lr;
            *(float2*)(Mb + (size_t)m0 * C + co) = make_float2(acc[mt][nt][0], acc[mt][nt][1]);
            *(float2*)(Mb + (size_t)(m0 + 8) * C + co) = make_float2(acc[mt][nt][2], acc[mt][nt][3]);
        }
    }
}

// ---------------- output transform: Y = A^T M A, + BN (+res) + ReLU ----------------
// block 256 = 4 tile-slots x 64 co-quads; grid 3136
template <int MODE>
__global__ __launch_bounds__(256) void wino_out(const float* __restrict__ resid,
                                                float* __restrict__ out) {
    __shared__ float st[16 * 257];   // MODE1 transpose buffer
    int t = threadIdx.x;
    int cog = t & 63, slot = t >> 6;
    int mp = blockIdx.x * 4 + slot;
    int n = mp / 196; int r0 = mp - n * 196;
    int ti = r0 / 14, tj = r0 - ti * 14;
    const float* scp = MODE ? g_s2 : g_s1;
    const float* bip = MODE ? g_b2 : g_b1;

    size_t mo = (size_t)mp * C + cog * 4;
    float4 m16[16];
    #pragma unroll
    for (int nu = 0; nu < 16; nu++)
        m16[nu] = *(const float4*)(g_Mf + nu * VSTRIDE + mo);

    __half2 oreg[4][2];
    #pragma unroll
    for (int k = 0; k < 4; k++) {
        float Mv[16];
        #pragma unroll
        for (int p = 0; p < 16; p++)
            Mv[p] = ((const float*)&m16[p])[k];
        float t0[4], t1[4];
        #pragma unroll
        for (int c = 0; c < 4; c++) {
            t0[c] = Mv[c] + Mv[4 + c] + Mv[8 + c];
            t1[c] = Mv[4 + c] - Mv[8 + c] - Mv[12 + c];
        }
        float y[4];
        y[0] = t0[0] + t0[1] + t0[2];
        y[1] = t0[1] - t0[2] - t0[3];
        y[2] = t1[0] + t1[1] + t1[2];
        y[3] = t1[1] - t1[2] - t1[3];
        const int co = cog * 4 + k;
        const float s = scp[co], bb = bip[co];
        #pragma unroll
        for (int p = 0; p < 4; p++) y[p] = y[p] * s + bb;

        if (MODE == 0) {
            #pragma unroll
            for (int p = 0; p < 4; p++) {
                __half hv = __float2half_rn(fmaxf(y[p], 0.f));
                int wdi = k >> 1;
                if ((k & 1) == 0) oreg[p][wdi] = __halves2half2(hv, hv);
                else oreg[p][wdi] = __halves2half2(__low2half(oreg[p][wdi]), hv);
            }
        } else {
            st[(slot * 4 + 0) * 257 + co] = y[0];
            st[(slot * 4 + 1) * 257 + co] = y[1];
            st[(slot * 4 + 2) * 257 + co] = y[2];
            st[(slot * 4 + 3) * 257 + co] = y[3];
        }
    }

    if (MODE == 0) {
        __half* dst = g_o1 + ((size_t)(n * NPAD + (2 * ti + 1) * 30 + 2 * tj + 1)) * C + cog * 4;
        *(uint2*)(dst)          = *(uint2*)oreg[0];
        *(uint2*)(dst + C)      = *(uint2*)oreg[1];
        *(uint2*)(dst + 30 * C) = *(uint2*)oreg[2];
        *(uint2*)(dst + 31 * C) = *(uint2*)oreg[3];
    } else {
        __syncthreads();
        const int l = t & 7, q = t >> 3;
        const int s2 = l >> 1, c2 = l & 1;
        const int r2 = q & 1, coq = q >> 1;          // coq 0..15
        const int mp2 = blockIdx.x * 4 + s2;
        const int n2 = mp2 / 196; int rr2 = mp2 - n2 * 196;
        const int ti2 = rr2 / 14, tj2 = rr2 - ti2 * 14;
        const int h = 2 * ti2 + r2, w = 2 * tj2 + c2;
        const int srow = (s2 * 4 + r2 * 2 + c2) * 257;
        #pragma unroll
        for (int cc = 0; cc < 16; cc++) {
            const int co2 = coq * 16 + cc;
            const size_t gi = ((size_t)n2 * C + co2) * HW + h * 28 + w;
            float v = st[srow + co2];
            out[gi] = fmaxf(v + resid[gi], 0.f);
        }
    }
}

// ---------------- launch ----------------
extern "C" void kernel_launch(void* const* d_in, const int* in_sizes, int n_in,
                              void* d_out, int out_size) {
    (void)in_sizes; (void)n_in; (void)out_size;
    const float* x  = (const float*)d_in[0];
    const float* w1 = (const float*)d_in[1];
    const float* g1 = (const float*)d_in[2];
    const float* b1 = (const float*)d_in[3];
    const float* m1 = (const float*)d_in[4];
    const float* v1 = (const float*)d_in[5];
    const float* w2 = (const float*)d_in[6];
    const float* g2 = (const float*)d_in[7];
    const float* b2 = (const float*)d_in[8];
    const float* m2 = (const float*)d_in[9];
    const float* v2 = (const float*)d_in[10];
    float* out = (float*)d_out;

    cudaFuncSetAttribute(gemm_wino<0>, cudaFuncAttributeMaxDynamicSharedMemorySize, 131072);
    cudaFuncSetAttribute(gemm_wino<1>, cudaFuncAttributeMaxDynamicSharedMemorySize, 131072);

    prep<<<dim3(257, 2), 256>>>(w1, w2, g1, b1, m1, v1, g2, b2, m2, v2);
    xpose<<<dim3(25, 8, 64), dim3(32, 8)>>>(x);

    // conv1
    wino_in<0><<<1568, 256>>>();
    gemm_wino<0><<<dim3(2, 98, 16), 256, 131072>>>();
    wino_out<0><<<3136, 256>>>(nullptr, nullptr);

    // conv2
    wino_in<1><<<1568, 256>>>();
    gemm_wino<1><<<dim3(2, 98, 16), 256, 131072>>>();
    wino_out<1><<<3136, 256>>>(x, out);
}

// round 8
// speedup vs baseline: 1.7999x; 1.1944x over previous
#include <cuda_runtime.h>
#include <cuda_fp16.h>
#include <cstdint>

// ---------------- constants ----------------
#define C     256
#define NB    64
#define HW    784
#define NPAD  900                 // 30*30 padded image
#define PADROWS (NB*NPAD)         // 57600
#define NTT   12544               // total 2x2 tiles = 64*14*14
#define VSTRIDE ((size_t)NTT*C)   // 3211264

// gemm tiling
#define GSTAGES 3
#define G_ABYTES 16384            // 128 rows x 64 fp16
#define G_BBYTES 16384
#define G_STG (G_ABYTES + G_BBYTES)        // 32 KB
#define G_SMEM (GSTAGES * G_STG)           // 96 KB -> 2 CTAs/SM

// ---------------- device scratch (only touched from device code!) ----------------
__device__ __half g_xh[PADROWS*C];   // padded NHWC input fp16 (halo stays 0)
__device__ __half g_o1[PADROWS*C];   // padded conv1 output fp16 (halo stays 0)
__device__ __half g_U1[16*C*C];      // transformed weights GgG^T
__device__ __half g_U2[16*C*C];
__device__ __half g_V[16*NTT*C];     // input transform (fp16)
__device__ float  g_Mf[16*NTT*C];    // gemm output (fp32 for numerics)
__device__ float g_s1[C], g_b1[C], g_s2[C], g_b2[C];

// ---------------- ptx helpers ----------------
__device__ __forceinline__ uint32_t smem_u32(const void* p) {
    uint32_t a;
    asm("{ .reg .u64 t; cvta.to.shared.u64 t, %1; cvt.u32.u64 %0, t; }" : "=r"(a) : "l"(p));
    return a;
}
__device__ __forceinline__ void cp16(uint32_t dst, const void* src) {
    asm volatile("cp.async.cg.shared.global [%0], [%1], 16;\n" :: "r"(dst), "l"(src));
}
__device__ __forceinline__ void cp_commit() { asm volatile("cp.async.commit_group;\n" ::); }
__device__ __forceinline__ void cp_wait1()  { asm volatile("cp.async.wait_group 1;\n" ::: "memory"); }
__device__ __forceinline__ void ldmx4(uint32_t* r, uint32_t addr) {
    asm volatile("ldmatrix.sync.aligned.m8n8.x4.shared.b16 {%0,%1,%2,%3}, [%4];"
        : "=r"(r[0]), "=r"(r[1]), "=r"(r[2]), "=r"(r[3]) : "r"(addr));
}
__device__ __forceinline__ void mma16816_f(float* c, const uint32_t* a, const uint32_t* b) {
    asm volatile("mma.sync.aligned.m16n8k16.row.col.f32.f16.f16.f32 "
        "{%0,%1,%2,%3}, {%4,%5,%6,%7}, {%8,%9}, {%0,%1,%2,%3};"
        : "+f"(c[0]), "+f"(c[1]), "+f"(c[2]), "+f"(c[3])
        : "r"(a[0]), "r"(a[1]), "r"(a[2]), "r"(a[3]), "r"(b[0]), "r"(b[1]));
}
#define SW(off) ((off) ^ (((off) >> 3) & 0x70))

// ---------------- prep: BN consts + weight transform U = G g G^T ----------------
__global__ void prep(const float* __restrict__ w1, const float* __restrict__ w2,
                     const float* __restrict__ g1, const float* __restrict__ b1,
                     const float* __restrict__ m1, const float* __restrict__ v1,
                     const float* __restrict__ g2, const float* __restrict__ b2,
                     const float* __restrict__ m2, const float* __restrict__ v2) {
    int co = blockIdx.x, which = blockIdx.y, ci = threadIdx.x;
    if (co == 256) {
        if (which == 0) {
            float inv = g1[ci] * rsqrtf(v1[ci] + 1e-5f);
            g_s1[ci] = 0.02f * inv; g_b1[ci] = b1[ci] - m1[ci] * inv;
        } else {
            float inv = g2[ci] * rsqrtf(v2[ci] + 1e-5f);
            g_s2[ci] = 0.02f * inv; g_b2[ci] = b2[ci] - m2[ci] * inv;
        }
        return;
    }
    const float* w = which ? w2 : w1;
    __half* U = which ? g_U2 : g_U1;
    float g[3][3];
    #pragma unroll
    for (int r = 0; r < 3; r++)
        #pragma unroll
        for (int c = 0; c < 3; c++) {
            float v = w[((co * C + ci) * 3 + r) * 3 + c];
            g[r][c] = (v > 0.f) ? 1.f : ((v < 0.f) ? -1.f : 0.f);
        }
    float T[4][3];
    #pragma unroll
    for (int c = 0; c < 3; c++) {
        T[0][c] = g[0][c];
        T[1][c] = 0.5f * (g[0][c] + g[1][c] + g[2][c]);
        T[2][c] = 0.5f * (g[0][c] - g[1][c] + g[2][c]);
        T[3][c] = g[2][c];
    }
    #pragma unroll
    for (int i = 0; i < 4; i++) {
        float u0 = T[i][0];
        float u1 = 0.5f * (T[i][0] + T[i][1] + T[i][2]);
        float u2 = 0.5f * (T[i][0] - T[i][1] + T[i][2]);
        float u3 = T[i][2];
        int base = co * C + ci;
        U[(i * 4 + 0) * (C * C) + base] = __float2half_rn(u0);
        U[(i * 4 + 1) * (C * C) + base] = __float2half_rn(u1);
        U[(i * 4 + 2) * (C * C) + base] = __float2half_rn(u2);
        U[(i * 4 + 3) * (C * C) + base] = __float2half_rn(u3);
    }
}

// ---------------- NCHW -> padded NHWC fp16 ----------------
__global__ void xpose(const float* __restrict__ x) {
    __shared__ float t[32][33];
    int n = blockIdx.z, hwt = blockIdx.x, ct = blockIdx.y;
    int tx = threadIdx.x, ty = threadIdx.y;
    int hw = hwt * 32 + tx;
    #pragma unroll
    for (int i = 0; i < 4; i++) {
        int c = ct * 32 + ty + i * 8;
        t[ty + i * 8][tx] = (hw < HW) ? x[((size_t)n * C + c) * HW + hw] : 0.f;
    }
    __syncthreads();
    #pragma unroll
    for (int i = 0; i < 4; i++) {
        int hw2 = hwt * 32 + ty + i * 8;
        int c = ct * 32 + tx;
        if (hw2 < HW) {
            int h = hw2 / 28, w = hw2 - h * 28;
            g_xh[((size_t)(n * NPAD + (h + 1) * 30 + w + 1)) * C + c] =
                __float2half_rn(t[tx][ty + i * 8]);
        }
    }
}

// ---------------- input transform: V = B^T d B ----------------
// block 256 = 8 tile-slots x 32 ci-octets; grid 1568
template <int WHICH>
__global__ __launch_bounds__(256) void wino_in() {
    const __half* src = WHICH ? g_o1 : g_xh;
    int t = threadIdx.x;
    int cig = t & 31, slot = t >> 5;
    int mp = blockIdx.x * 8 + slot;
    int n = mp / 196; int r0 = mp - n * 196;
    int ti = r0 / 14, tj = r0 - ti * 14;
    const __half* base = src + ((size_t)(n * NPAD + 2 * ti * 30 + 2 * tj)) * C + cig * 8;

    uint4 d16[16];
    #pragma unroll
    for (int i = 0; i < 4; i++)
        #pragma unroll
        for (int j = 0; j < 4; j++)
            d16[i * 4 + j] = *(const uint4*)(base + (size_t)(i * 30 + j) * C);

    __half2 vout[16][4];
    #pragma unroll
    for (int k = 0; k < 8; k++) {
        float d[4][4];
        #pragma unroll
        for (int p = 0; p < 16; p++) {
            uint32_t wd = ((const uint32_t*)&d16[p])[k >> 1];
            float2 f = __half22float2(*(__half2*)&wd);
            d[p >> 2][p & 3] = (k & 1) ? f.y : f.x;
        }
        float tt[4][4];
        #pragma unroll
        for (int c = 0; c < 4; c++) {
            tt[0][c] = d[0][c] - d[2][c];
            tt[1][c] = d[1][c] + d[2][c];
            tt[2][c] = d[2][c] - d[1][c];
            tt[3][c] = d[1][c] - d[3][c];
        }
        #pragma unroll
        for (int i = 0; i < 4; i++) {
            float v[4];
            v[0] = tt[i][0] - tt[i][2];
            v[1] = tt[i][1] + tt[i][2];
            v[2] = tt[i][2] - tt[i][1];
            v[3] = tt[i][1] - tt[i][3];
            #pragma unroll
            for (int j = 0; j < 4; j++) {
                __half hv = __float2half_rn(v[j]);
                int nu = i * 4 + j, wdi = k >> 1;
                if ((k & 1) == 0) vout[nu][wdi] = __halves2half2(hv, hv);
                else vout[nu][wdi] = __halves2half2(__low2half(vout[nu][wdi]), hv);
            }
        }
    }
    size_t mo = (size_t)mp * C + cig * 8;
    #pragma unroll
    for (int nu = 0; nu < 16; nu++)
        *(uint4*)(g_V + nu * VSTRIDE + mo) = *(uint4*)vout[nu];
}

// ---------------- batched GEMM: M[nu] = V[nu] * U[nu]^T ----------------
// grid (2, 98, 16), block 256 (8 warps 2x4, warp tile 64x32), 3-stage 96KB, occ 2
template <int WHICH>
__global__ __launch_bounds__(256, 2) void gemm_wino() {
    extern __shared__ char smem[];
    const uint32_t sb = smem_u32(smem);
    const int bn_ = blockIdx.x, bm = blockIdx.y, nu = blockIdx.z;
    const __half* Vb = g_V + (size_t)nu * VSTRIDE;
    const __half* Ub = (WHICH ? g_U2 : g_U1) + (size_t)nu * (C * C);

    const int tid = threadIdx.x;
    const int wid = tid >> 5, lane = tid & 31;
    const int row = tid >> 1, hf = tid & 1;
    const __half* Arow = Vb + (size_t)(bm * 128 + row) * C + hf * 32;
    const __half* Brow = Ub + (size_t)(bn_ * 128 + row) * C + hf * 32;

    auto loadChunk = [&](int k) {
        const uint32_t base = sb + (k % GSTAGES) * G_STG;
        const uint32_t ro = (uint32_t)row * 128 + hf * 64;
        #pragma unroll
        for (int i = 0; i < 4; i++) {
            uint32_t o = ro + i * 16;
            cp16(base + SW(o), Arow + k * 64 + i * 8);
            cp16(base + G_ABYTES + SW(o), Brow + k * 64 + i * 8);
        }
        cp_commit();
    };

    const int wm = wid & 1, wn = wid >> 1;
    const int lq = lane >> 3, l7 = lane & 7;
    const int aro = (lq & 1) * 8 + l7, aqh = lq >> 1;
    const int bro = (lq >> 1) * 8 + l7, bqh = lq & 1;

    float acc[4][4][4];
    #pragma unroll
    for (int i = 0; i < 4; i++)
        #pragma unroll
        for (int j = 0; j < 4; j++)
            #pragma unroll
            for (int k = 0; k < 4; k++) acc[i][j][k] = 0.f;

    loadChunk(0);
    loadChunk(1);

    #pragma unroll
    for (int k = 0; k < 4; k++) {
        cp_wait1();
        __syncthreads();
        if (k + 2 < 4) loadChunk(k + 2); else cp_commit();

        const uint32_t aB = sb + (k % GSTAGES) * G_STG + (uint32_t)(wm * 64) * 128;
        const uint32_t bB = sb + (k % GSTAGES) * G_STG + G_ABYTES + (uint32_t)(wn * 32) * 128;

        #pragma unroll
        for (int ks = 0; ks < 4; ks++) {
            uint32_t af[4][4];
            #pragma unroll
            for (int mt = 0; mt < 4; mt++) {
                int rw = mt * 16 + aro;
                uint32_t cx = (uint32_t)(((ks * 2 + aqh) ^ (rw & 7)) * 16);
                ldmx4(af[mt], aB + (uint32_t)rw * 128 + cx);
            }
            uint32_t bf[2][4];
            #pragma unroll
            for (int nt2 = 0; nt2 < 2; nt2++) {
                int rw = nt2 * 16 + bro;
                uint32_t cx = (uint32_t)(((ks * 2 + bqh) ^ (rw & 7)) * 16);
                ldmx4(bf[nt2], bB + (uint32_t)rw * 128 + cx);
            }
            #pragma unroll
            for (int mt = 0; mt < 4; mt++)
                #pragma unroll
                for (int nt = 0; nt < 4; nt++)
                    mma16816_f(acc[mt][nt], af[mt], &bf[nt >> 1][(nt & 1) * 2]);
        }
    }

    // epilogue: fp32 M
    const int lr = lane >> 2, lc = (lane & 3) * 2;
    float* Mb = g_Mf + (size_t)nu * VSTRIDE;
    #pragma unroll
    for (int nt = 0; nt < 4; nt++) {
        const int co = bn_ * 128 + wn * 32 + nt * 8 + lc;
        #pragma unroll
        for (int mt = 0; mt < 4; mt++) {
            const int m0 = bm * 128 + wm * 64 + mt * 16 + lr;
            *(float2*)(Mb + (size_t)m0 * C + co) = make_float2(acc[mt][nt][0], acc[mt][nt][1]);
            *(float2*)(Mb + (size_t)(m0 + 8) * C + co) = make_float2(acc[mt][nt][2], acc[mt][nt][3]);
        }
    }
}

// ---------------- output transform: Y = A^T M A, + BN (+res) + ReLU ----------------
// block 256 = 4 tile-slots x 64 co-quads; grid 3136
template <int MODE>
__global__ __launch_bounds__(256) void wino_out(const float* __restrict__ resid,
                                                float* __restrict__ out) {
    __shared__ float st[16 * 257];   // MODE1 transpose buffer
    int t = threadIdx.x;
    int cog = t & 63, slot = t >> 6;
    int mp = blockIdx.x * 4 + slot;
    int n = mp / 196; int r0 = mp - n * 196;
    int ti = r0 / 14, tj = r0 - ti * 14;
    const float* scp = MODE ? g_s2 : g_s1;
    const float* bip = MODE ? g_b2 : g_b1;

    size_t mo = (size_t)mp * C + cog * 4;
    float4 m16[16];
    #pragma unroll
    for (int nu = 0; nu < 16; nu++)
        m16[nu] = *(const float4*)(g_Mf + nu * VSTRIDE + mo);

    __half2 oreg[4][2];
    #pragma unroll
    for (int k = 0; k < 4; k++) {
        float Mv[16];
        #pragma unroll
        for (int p = 0; p < 16; p++)
            Mv[p] = ((const float*)&m16[p])[k];
        float t0[4], t1[4];
        #pragma unroll
        for (int c = 0; c < 4; c++) {
            t0[c] = Mv[c] + Mv[4 + c] + Mv[8 + c];
            t1[c] = Mv[4 + c] - Mv[8 + c] - Mv[12 + c];
        }
        float y[4];
        y[0] = t0[0] + t0[1] + t0[2];
        y[1] = t0[1] - t0[2] - t0[3];
        y[2] = t1[0] + t1[1] + t1[2];
        y[3] = t1[1] - t1[2] - t1[3];
        const int co = cog * 4 + k;
        const float s = scp[co], bb = bip[co];
        #pragma unroll
        for (int p = 0; p < 4; p++) y[p] = y[p] * s + bb;

        if (MODE == 0) {
            #pragma unroll
            for (int p = 0; p < 4; p++) {
                __half hv = __float2half_rn(fmaxf(y[p], 0.f));
                int wdi = k >> 1;
                if ((k & 1) == 0) oreg[p][wdi] = __halves2half2(hv, hv);
                else oreg[p][wdi] = __halves2half2(__low2half(oreg[p][wdi]), hv);
            }
        } else {
            st[(slot * 4 + 0) * 257 + co] = y[0];
            st[(slot * 4 + 1) * 257 + co] = y[1];
            st[(slot * 4 + 2) * 257 + co] = y[2];
            st[(slot * 4 + 3) * 257 + co] = y[3];
        }
    }

    if (MODE == 0) {
        __half* dst = g_o1 + ((size_t)(n * NPAD + (2 * ti + 1) * 30 + 2 * tj + 1)) * C + cog * 4;
        *(uint2*)(dst)          = *(uint2*)oreg[0];
        *(uint2*)(dst + C)      = *(uint2*)oreg[1];
        *(uint2*)(dst + 30 * C) = *(uint2*)oreg[2];
        *(uint2*)(dst + 31 * C) = *(uint2*)oreg[3];
    } else {
        __syncthreads();
        const int l = t & 7, q = t >> 3;
        const int s2 = l >> 1, c2 = l & 1;
        const int r2 = q & 1, coq = q >> 1;          // coq 0..15
        const int mp2 = blockIdx.x * 4 + s2;
        const int n2 = mp2 / 196; int rr2 = mp2 - n2 * 196;
        const int ti2 = rr2 / 14, tj2 = rr2 - ti2 * 14;
        const int h = 2 * ti2 + r2, w = 2 * tj2 + c2;
        const int srow = (s2 * 4 + r2 * 2 + c2) * 257;
        #pragma unroll
        for (int cc = 0; cc < 16; cc++) {
            const int co2 = coq * 16 + cc;
            const size_t gi = ((size_t)n2 * C + co2) * HW + h * 28 + w;
            float v = st[srow + co2];
            out[gi] = fmaxf(v + resid[gi], 0.f);
        }
    }
}

// ---------------- launch ----------------
extern "C" void kernel_launch(void* const* d_in, const int* in_sizes, int n_in,
                              void* d_out, int out_size) {
    (void)in_sizes; (void)n_in; (void)out_size;
    const float* x  = (const float*)d_in[0];
    const float* w1 = (const float*)d_in[1];
    const float* g1 = (const float*)d_in[2];
    const float* b1 = (const float*)d_in[3];
    const float* m1 = (const float*)d_in[4];
    const float* v1 = (const float*)d_in[5];
    const float* w2 = (const float*)d_in[6];
    const float* g2 = (const float*)d_in[7];
    const float* b2 = (const float*)d_in[8];
    const float* m2 = (const float*)d_in[9];
    const float* v2 = (const float*)d_in[10];
    float* out = (float*)d_out;

    cudaFuncSetAttribute(gemm_wino<0>, cudaFuncAttributeMaxDynamicSharedMemorySize, G_SMEM);
    cudaFuncSetAttribute(gemm_wino<1>, cudaFuncAttributeMaxDynamicSharedMemorySize, G_SMEM);

    prep<<<dim3(257, 2), 256>>>(w1, w2, g1, b1, m1, v1, g2, b2, m2, v2);
    xpose<<<dim3(25, 8, 64), dim3(32, 8)>>>(x);

    // conv1
    wino_in<0><<<1568, 256>>>();
    gemm_wino<0><<<dim3(2, 98, 16), 256, G_SMEM>>>();
    wino_out<0><<<3136, 256>>>(nullptr, nullptr);

    // conv2
    wino_in<1><<<1568, 256>>>();
    gemm_wino<1><<<dim3(2, 98, 16), 256, G_SMEM>>>();
    wino_out<1><<<3136, 256>>>(x, out);
}

// round 9
// speedup vs baseline: 2.0311x; 1.1285x over previous
#include <cuda_runtime.h>
#include <cuda_fp16.h>
#include <cstdint>

// ---------------- constants ----------------
#define C     256
#define NB    64
#define HW    784
#define NPAD  900                 // 30*30 padded image
#define PADROWS (NB*NPAD)         // 57600
#define NTT   12544               // total 2x2 tiles = 64*14*14
#define VSTRIDE ((size_t)NTT*C)   // 3211264

// gemm tiling
#define GSTAGES 3
#define G_ABYTES 16384            // 128 rows x 64 fp16
#define G_BBYTES 16384
#define G_STG (G_ABYTES + G_BBYTES)        // 32 KB
#define G_SMEM (GSTAGES * G_STG)           // 96 KB -> 2 CTAs/SM

// ---------------- device scratch (only touched from device code!) ----------------
__device__ __half g_xh[PADROWS*C];   // padded NHWC input fp16 (halo stays 0)
__device__ __half g_o1[PADROWS*C];   // padded conv1 output fp16 (halo stays 0)
__device__ __half g_U1[16*C*C];      // transformed weights GgG^T
__device__ __half g_U2[16*C*C];
__device__ __half g_V[16*NTT*C];     // input transform (fp16)
__device__ __half g_Mh[16*NTT*C];    // gemm output (fp16)
__device__ float g_s1[C], g_b1[C], g_s2[C], g_b2[C];

// ---------------- ptx helpers ----------------
__device__ __forceinline__ uint32_t smem_u32(const void* p) {
    uint32_t a;
    asm("{ .reg .u64 t; cvta.to.shared.u64 t, %1; cvt.u32.u64 %0, t; }" : "=r"(a) : "l"(p));
    return a;
}
__device__ __forceinline__ void cp16(uint32_t dst, const void* src) {
    asm volatile("cp.async.cg.shared.global [%0], [%1], 16;\n" :: "r"(dst), "l"(src));
}
__device__ __forceinline__ void cp_commit() { asm volatile("cp.async.commit_group;\n" ::); }
__device__ __forceinline__ void cp_wait1()  { asm volatile("cp.async.wait_group 1;\n" ::: "memory"); }
__device__ __forceinline__ void ldmx4(uint32_t* r, uint32_t addr) {
    asm volatile("ldmatrix.sync.aligned.m8n8.x4.shared.b16 {%0,%1,%2,%3}, [%4];"
        : "=r"(r[0]), "=r"(r[1]), "=r"(r[2]), "=r"(r[3]) : "r"(addr));
}
__device__ __forceinline__ void mma16816_f(float* c, const uint32_t* a, const uint32_t* b) {
    asm volatile("mma.sync.aligned.m16n8k16.row.col.f32.f16.f16.f32 "
        "{%0,%1,%2,%3}, {%4,%5,%6,%7}, {%8,%9}, {%0,%1,%2,%3};"
        : "+f"(c[0]), "+f"(c[1]), "+f"(c[2]), "+f"(c[3])
        : "r"(a[0]), "r"(a[1]), "r"(a[2]), "r"(a[3]), "r"(b[0]), "r"(b[1]));
}
#define SW(off) ((off) ^ (((off) >> 3) & 0x70))

// ---------------- prep: BN consts + weight transform U = G g G^T ----------------
__global__ void prep(const float* __restrict__ w1, const float* __restrict__ w2,
                     const float* __restrict__ g1, const float* __restrict__ b1,
                     const float* __restrict__ m1, const float* __restrict__ v1,
                     const float* __restrict__ g2, const float* __restrict__ b2,
                     const float* __restrict__ m2, const float* __restrict__ v2) {
    int co = blockIdx.x, which = blockIdx.y, ci = threadIdx.x;
    if (co == 256) {
        if (which == 0) {
            float inv = g1[ci] * rsqrtf(v1[ci] + 1e-5f);
            g_s1[ci] = 0.02f * inv; g_b1[ci] = b1[ci] - m1[ci] * inv;
        } else {
            float inv = g2[ci] * rsqrtf(v2[ci] + 1e-5f);
            g_s2[ci] = 0.02f * inv; g_b2[ci] = b2[ci] - m2[ci] * inv;
        }
        return;
    }
    const float* w = which ? w2 : w1;
    __half* U = which ? g_U2 : g_U1;
    float g[3][3];
    #pragma unroll
    for (int r = 0; r < 3; r++)
        #pragma unroll
        for (int c = 0; c < 3; c++) {
            float v = w[((co * C + ci) * 3 + r) * 3 + c];
            g[r][c] = (v > 0.f) ? 1.f : ((v < 0.f) ? -1.f : 0.f);
        }
    float T[4][3];
    #pragma unroll
    for (int c = 0; c < 3; c++) {
        T[0][c] = g[0][c];
        T[1][c] = 0.5f * (g[0][c] + g[1][c] + g[2][c]);
        T[2][c] = 0.5f * (g[0][c] - g[1][c] + g[2][c]);
        T[3][c] = g[2][c];
    }
    #pragma unroll
    for (int i = 0; i < 4; i++) {
        float u0 = T[i][0];
        float u1 = 0.5f * (T[i][0] + T[i][1] + T[i][2]);
        float u2 = 0.5f * (T[i][0] - T[i][1] + T[i][2]);
        float u3 = T[i][2];
        int base = co * C + ci;
        U[(i * 4 + 0) * (C * C) + base] = __float2half_rn(u0);
        U[(i * 4 + 1) * (C * C) + base] = __float2half_rn(u1);
        U[(i * 4 + 2) * (C * C) + base] = __float2half_rn(u2);
        U[(i * 4 + 3) * (C * C) + base] = __float2half_rn(u3);
    }
}

// ---------------- NCHW -> padded NHWC fp16 ----------------
__global__ void xpose(const float* __restrict__ x) {
    __shared__ float t[32][33];
    int n = blockIdx.z, hwt = blockIdx.x, ct = blockIdx.y;
    int tx = threadIdx.x, ty = threadIdx.y;
    int hw = hwt * 32 + tx;
    #pragma unroll
    for (int i = 0; i < 4; i++) {
        int c = ct * 32 + ty + i * 8;
        t[ty + i * 8][tx] = (hw < HW) ? x[((size_t)n * C + c) * HW + hw] : 0.f;
    }
    __syncthreads();
    #pragma unroll
    for (int i = 0; i < 4; i++) {
        int hw2 = hwt * 32 + ty + i * 8;
        int c = ct * 32 + tx;
        if (hw2 < HW) {
            int h = hw2 / 28, w = hw2 - h * 28;
            g_xh[((size_t)(n * NPAD + (h + 1) * 30 + w + 1)) * C + c] =
                __float2half_rn(t[tx][ty + i * 8]);
        }
    }
}

// ---------------- input transform: V = B^T d B ----------------
// block 256 = 8 tile-slots x 32 ci-octets; grid 1568
template <int WHICH>
__global__ __launch_bounds__(256) void wino_in() {
    const __half* src = WHICH ? g_o1 : g_xh;
    int t = threadIdx.x;
    int cig = t & 31, slot = t >> 5;
    int mp = blockIdx.x * 8 + slot;
    int n = mp / 196; int r0 = mp - n * 196;
    int ti = r0 / 14, tj = r0 - ti * 14;
    const __half* base = src + ((size_t)(n * NPAD + 2 * ti * 30 + 2 * tj)) * C + cig * 8;

    uint4 d16[16];
    #pragma unroll
    for (int i = 0; i < 4; i++)
        #pragma unroll
        for (int j = 0; j < 4; j++)
            d16[i * 4 + j] = *(const uint4*)(base + (size_t)(i * 30 + j) * C);

    __half2 vout[16][4];
    #pragma unroll
    for (int k = 0; k < 8; k++) {
        float d[4][4];
        #pragma unroll
        for (int p = 0; p < 16; p++) {
            uint32_t wd = ((const uint32_t*)&d16[p])[k >> 1];
            float2 f = __half22float2(*(__half2*)&wd);
            d[p >> 2][p & 3] = (k & 1) ? f.y : f.x;
        }
        float tt[4][4];
        #pragma unroll
        for (int c = 0; c < 4; c++) {
            tt[0][c] = d[0][c] - d[2][c];
            tt[1][c] = d[1][c] + d[2][c];
            tt[2][c] = d[2][c] - d[1][c];
            tt[3][c] = d[1][c] - d[3][c];
        }
        #pragma unroll
        for (int i = 0; i < 4; i++) {
            float v[4];
            v[0] = tt[i][0] - tt[i][2];
            v[1] = tt[i][1] + tt[i][2];
            v[2] = tt[i][2] - tt[i][1];
            v[3] = tt[i][1] - tt[i][3];
            #pragma unroll
            for (int j = 0; j < 4; j++) {
                __half hv = __float2half_rn(v[j]);
                int nu = i * 4 + j, wdi = k >> 1;
                if ((k & 1) == 0) vout[nu][wdi] = __halves2half2(hv, hv);
                else vout[nu][wdi] = __halves2half2(__low2half(vout[nu][wdi]), hv);
            }
        }
    }
    size_t mo = (size_t)mp * C + cig * 8;
    #pragma unroll
    for (int nu = 0; nu < 16; nu++)
        *(uint4*)(g_V + nu * VSTRIDE + mo) = *(uint4*)vout[nu];
}

// ---------------- batched GEMM: M[nu] = V[nu] * U[nu]^T ----------------
// grid (2, 98, 16), block 256 (8 warps 2x4, warp tile 64x32), 3-stage 96KB, occ 2
template <int WHICH>
__global__ __launch_bounds__(256, 2) void gemm_wino() {
    extern __shared__ char smem[];
    const uint32_t sb = smem_u32(smem);
    const int bn_ = blockIdx.x, bm = blockIdx.y, nu = blockIdx.z;
    const __half* Vb = g_V + (size_t)nu * VSTRIDE;
    const __half* Ub = (WHICH ? g_U2 : g_U1) + (size_t)nu * (C * C);

    const int tid = threadIdx.x;
    const int wid = tid >> 5, lane = tid & 31;
    const int row = tid >> 1, hf = tid & 1;
    const __half* Arow = Vb + (size_t)(bm * 128 + row) * C + hf * 32;
    const __half* Brow = Ub + (size_t)(bn_ * 128 + row) * C + hf * 32;

    auto loadChunk = [&](int k) {
        const uint32_t base = sb + (k % GSTAGES) * G_STG;
        const uint32_t ro = (uint32_t)row * 128 + hf * 64;
        #pragma unroll
        for (int i = 0; i < 4; i++) {
            uint32_t o = ro + i * 16;
            cp16(base + SW(o), Arow + k * 64 + i * 8);
            cp16(base + G_ABYTES + SW(o), Brow + k * 64 + i * 8);
        }
        cp_commit();
    };

    const int wm = wid & 1, wn = wid >> 1;
    const int lq = lane >> 3, l7 = lane & 7;
    const int aro = (lq & 1) * 8 + l7, aqh = lq >> 1;
    const int bro = (lq >> 1) * 8 + l7, bqh = lq & 1;

    float acc[4][4][4];
    #pragma unroll
    for (int i = 0; i < 4; i++)
        #pragma unroll
        for (int j = 0; j < 4; j++)
            #pragma unroll
            for (int k = 0; k < 4; k++) acc[i][j][k] = 0.f;

    loadChunk(0);
    loadChunk(1);

    #pragma unroll
    for (int k = 0; k < 4; k++) {
        cp_wait1();
        __syncthreads();
        if (k + 2 < 4) loadChunk(k + 2); else cp_commit();

        const uint32_t aB = sb + (k % GSTAGES) * G_STG + (uint32_t)(wm * 64) * 128;
        const uint32_t bB = sb + (k % GSTAGES) * G_STG + G_ABYTES + (uint32_t)(wn * 32) * 128;

        #pragma unroll
        for (int ks = 0; ks < 4; ks++) {
            uint32_t af[4][4];
            #pragma unroll
            for (int mt = 0; mt < 4; mt++) {
                int rw = mt * 16 + aro;
                uint32_t cx = (uint32_t)(((ks * 2 + aqh) ^ (rw & 7)) * 16);
                ldmx4(af[mt], aB + (uint32_t)rw * 128 + cx);
            }
            uint32_t bf[2][4];
            #pragma unroll
            for (int nt2 = 0; nt2 < 2; nt2++) {
                int rw = nt2 * 16 + bro;
                uint32_t cx = (uint32_t)(((ks * 2 + bqh) ^ (rw & 7)) * 16);
                ldmx4(bf[nt2], bB + (uint32_t)rw * 128 + cx);
            }
            #pragma unroll
            for (int mt = 0; mt < 4; mt++)
                #pragma unroll
                for (int nt = 0; nt < 4; nt++)
                    mma16816_f(acc[mt][nt], af[mt], &bf[nt >> 1][(nt & 1) * 2]);
        }
    }

    // epilogue: fp16 M
    const int lr = lane >> 2, lc = (lane & 3) * 2;
    __half* Mb = g_Mh + (size_t)nu * VSTRIDE;
    #pragma unroll
    for (int nt = 0; nt < 4; nt++) {
        const int co = bn_ * 128 + wn * 32 + nt * 8 + lc;
        #pragma unroll
        for (int mt = 0; mt < 4; mt++) {
            const int m0 = bm * 128 + wm * 64 + mt * 16 + lr;
            *(__half2*)(Mb + (size_t)m0 * C + co) = __floats2half2_rn(acc[mt][nt][0], acc[mt][nt][1]);
            *(__half2*)(Mb + (size_t)(m0 + 8) * C + co) = __floats2half2_rn(acc[mt][nt][2], acc[mt][nt][3]);
        }
    }
}

// ---------------- output transform: Y = A^T M A, + BN (+res) + ReLU ----------------
// block 256 = 4 tile-slots x 64 co-quads; grid 3136
template <int MODE>
__global__ __launch_bounds__(256) void wino_out(const float* __restrict__ resid,
                                                float* __restrict__ out) {
    __shared__ float st[16 * 257];   // MODE1 transpose buffer
    int t = threadIdx.x;
    int cog = t & 63, slot = t >> 6;
    int mp = blockIdx.x * 4 + slot;
    int n = mp / 196; int r0 = mp - n * 196;
    int ti = r0 / 14, tj = r0 - ti * 14;
    const float* scp = MODE ? g_s2 : g_s1;
    const float* bip = MODE ? g_b2 : g_b1;

    size_t mo = (size_t)mp * C + cog * 4;
    uint2 m16[16];
    #pragma unroll
    for (int nu = 0; nu < 16; nu++)
        m16[nu] = *(const uint2*)(g_Mh + nu * VSTRIDE + mo);

    __half2 oreg[4][2];
    #pragma unroll
    for (int k = 0; k < 4; k++) {
        float Mv[16];
        #pragma unroll
        for (int p = 0; p < 16; p++) {
            uint32_t wd = ((const uint32_t*)&m16[p])[k >> 1];
            float2 f = __half22float2(*(__half2*)&wd);
            Mv[p] = (k & 1) ? f.y : f.x;
        }
        float t0[4], t1[4];
        #pragma unroll
        for (int c = 0; c < 4; c++) {
            t0[c] = Mv[c] + Mv[4 + c] + Mv[8 + c];
            t1[c] = Mv[4 + c] - Mv[8 + c] - Mv[12 + c];
        }
        float y[4];
        y[0] = t0[0] + t0[1] + t0[2];
        y[1] = t0[1] - t0[2] - t0[3];
        y[2] = t1[0] + t1[1] + t1[2];
        y[3] = t1[1] - t1[2] - t1[3];
        const int co = cog * 4 + k;
        const float s = scp[co], bb = bip[co];
        #pragma unroll
        for (int p = 0; p < 4; p++) y[p] = y[p] * s + bb;

        if (MODE == 0) {
            #pragma unroll
            for (int p = 0; p < 4; p++) {
                __half hv = __float2half_rn(fmaxf(y[p], 0.f));
                int wdi = k >> 1;
                if ((k & 1) == 0) oreg[p][wdi] = __halves2half2(hv, hv);
                else oreg[p][wdi] = __halves2half2(__low2half(oreg[p][wdi]), hv);
            }
        } else {
            st[(slot * 4 + 0) * 257 + co] = y[0];
            st[(slot * 4 + 1) * 257 + co] = y[1];
            st[(slot * 4 + 2) * 257 + co] = y[2];
            st[(slot * 4 + 3) * 257 + co] = y[3];
        }
    }

    if (MODE == 0) {
        __half* dst = g_o1 + ((size_t)(n * NPAD + (2 * ti + 1) * 30 + 2 * tj + 1)) * C + cog * 4;
        *(uint2*)(dst)          = *(uint2*)oreg[0];
        *(uint2*)(dst + C)      = *(uint2*)oreg[1];
        *(uint2*)(dst + 30 * C) = *(uint2*)oreg[2];
        *(uint2*)(dst + 31 * C) = *(uint2*)oreg[3];
    } else {
        __syncthreads();
        const int l = t & 7, q = t >> 3;
        const int s2 = l >> 1, c2 = l & 1;
        const int r2 = q & 1, coq = q >> 1;          // coq 0..15
        const int mp2 = blockIdx.x * 4 + s2;
        const int n2 = mp2 / 196; int rr2 = mp2 - n2 * 196;
        const int ti2 = rr2 / 14, tj2 = rr2 - ti2 * 14;
        const int h = 2 * ti2 + r2, w = 2 * tj2 + c2;
        const int srow = (s2 * 4 + r2 * 2 + c2) * 257;
        #pragma unroll
        for (int cc = 0; cc < 16; cc++) {
            const int co2 = coq * 16 + cc;
            const size_t gi = ((size_t)n2 * C + co2) * HW + h * 28 + w;
            float v = st[srow + co2];
            out[gi] = fmaxf(v + resid[gi], 0.f);
        }
    }
}

// ---------------- launch ----------------
extern "C" void kernel_launch(void* const* d_in, const int* in_sizes, int n_in,
                              void* d_out, int out_size) {
    (void)in_sizes; (void)n_in; (void)out_size;
    const float* x  = (const float*)d_in[0];
    const float* w1 = (const float*)d_in[1];
    const float* g1 = (const float*)d_in[2];
    const float* b1 = (const float*)d_in[3];
    const float* m1 = (const float*)d_in[4];
    const float* v1 = (const float*)d_in[5];
    const float* w2 = (const float*)d_in[6];
    const float* g2 = (const float*)d_in[7];
    const float* b2 = (const float*)d_in[8];
    const float* m2 = (const float*)d_in[9];
    const float* v2 = (const float*)d_in[10];
    float* out = (float*)d_out;

    cudaFuncSetAttribute(gemm_wino<0>, cudaFuncAttributeMaxDynamicSharedMemorySize, G_SMEM);
    cudaFuncSetAttribute(gemm_wino<1>, cudaFuncAttributeMaxDynamicSharedMemorySize, G_SMEM);

    prep<<<dim3(257, 2), 256>>>(w1, w2, g1, b1, m1, v1, g2, b2, m2, v2);
    xpose<<<dim3(25, 8, 64), dim3(32, 8)>>>(x);

    // conv1
    wino_in<0><<<1568, 256>>>();
    gemm_wino<0><<<dim3(2, 98, 16), 256, G_SMEM>>>();
    wino_out<0><<<3136, 256>>>(nullptr, nullptr);

    // conv2
    wino_in<1><<<1568, 256>>>();
    gemm_wino<1><<<dim3(2, 98, 16), 256, G_SMEM>>>();
    wino_out<1><<<3136, 256>>>(x, out);
}